// round 1
// baseline (speedup 1.0000x reference)
#include <cuda_runtime.h>
#include <math.h>

#define B_  2
#define T_  2048
#define E_  768
#define H_  12
#define D_  64
#define M_  (B_*T_)    // 4096 rows
#define FF_ (4*E_)     // 3072
#define BH_ (B_*H_)    // 24

// ---------------- scratch (static __device__, no allocation) ----------------
__device__ float g_h1 [M_*E_];                    // LN1 output
__device__ float g_q  [M_*E_];                    // [B,H,T,D]
__device__ float g_k  [M_*E_];
__device__ float g_v  [M_*E_];
__device__ float g_s  [(size_t)BH_*T_*T_];        // attention scores / probs (402 MB)
__device__ float g_ctx[M_*E_];                    // context, [B,T,H,D] flat = [4096,768]
__device__ float g_x2 [M_*E_];                    // post-attention residual stream
__device__ float g_h2 [M_*E_];                    // LN2 output
__device__ float g_mid[M_*FF_];                   // MLP hidden

// ---------------- LayerNorm (ddof=1) ----------------
__global__ void __launch_bounds__(256)
ln_kernel(const float* __restrict__ x, const float* __restrict__ sc,
          const float* __restrict__ sh, float* __restrict__ out)
{
    int row = blockIdx.x;
    const float* xr = x + (size_t)row * E_;
    float s = 0.f, s2 = 0.f;
    for (int i = threadIdx.x; i < E_; i += 256) { float v = xr[i]; s += v; s2 += v*v; }
    __shared__ float rs[8], rs2[8];
    #pragma unroll
    for (int o = 16; o; o >>= 1) {
        s  += __shfl_xor_sync(0xffffffffu, s,  o);
        s2 += __shfl_xor_sync(0xffffffffu, s2, o);
    }
    if ((threadIdx.x & 31) == 0) { rs[threadIdx.x>>5] = s; rs2[threadIdx.x>>5] = s2; }
    __syncthreads();
    float ts = 0.f, ts2 = 0.f;
    #pragma unroll
    for (int i = 0; i < 8; i++) { ts += rs[i]; ts2 += rs2[i]; }
    float mean = ts * (1.f / E_);
    float var  = (ts2 - ts * mean) * (1.f / (E_ - 1));   // unbiased
    float rstd = rsqrtf(var + 1e-5f);
    float* outr = out + (size_t)row * E_;
    for (int i = threadIdx.x; i < E_; i += 256)
        outr[i] = sc[i] * (xr[i] - mean) * rstd + sh[i];
}

// ---------------- generic tiled SGEMM, 64x64 tile, 4x4 micro-tile ----------------
enum { EPI_NONE = 0, EPI_QKV = 1, EPI_BIAS_RESID = 2, EPI_BIAS_GELU = 3 };

template<int EPI>
__global__ void __launch_bounds__(256)
sgemm(const float* __restrict__ A, const float* __restrict__ Bm,
      const float* __restrict__ bias, const float* __restrict__ resid,
      float* __restrict__ C, int M, int N, int K)
{
    __shared__ float As[16][64];   // [k][m] (transposed)
    __shared__ float Bs[16][64];   // [k][n]
    const int m0 = blockIdx.y * 64, n0 = blockIdx.x * 64;
    const int tx = threadIdx.x & 15, ty = threadIdx.x >> 4;
    const int lr = threadIdx.x >> 2, lc = (threadIdx.x & 3) * 4;   // A-tile loader
    const int br = threadIdx.x >> 4, bc = (threadIdx.x & 15) * 4;  // B-tile loader
    float acc[4][4] = {};

    for (int k0 = 0; k0 < K; k0 += 16) {
        float4 av = *(const float4*)&A[(size_t)(m0 + lr) * K + k0 + lc];
        As[lc+0][lr] = av.x; As[lc+1][lr] = av.y; As[lc+2][lr] = av.z; As[lc+3][lr] = av.w;
        *(float4*)&Bs[br][bc] = *(const float4*)&Bm[(size_t)(k0 + br) * N + n0 + bc];
        __syncthreads();
        #pragma unroll
        for (int k = 0; k < 16; k++) {
            float4 a = *(const float4*)&As[k][ty*4];
            float4 b = *(const float4*)&Bs[k][tx*4];
            float ar[4] = {a.x,a.y,a.z,a.w}, brr[4] = {b.x,b.y,b.z,b.w};
            #pragma unroll
            for (int i = 0; i < 4; i++)
                #pragma unroll
                for (int j = 0; j < 4; j++) acc[i][j] += ar[i]*brr[j];
        }
        __syncthreads();
    }

    #pragma unroll
    for (int i = 0; i < 4; i++) {
        int m = m0 + ty*4 + i;
        #pragma unroll
        for (int j = 0; j < 4; j++) {
            int n = n0 + tx*4 + j;
            float v = acc[i][j];
            if (EPI == EPI_QKV) {
                // scatter [m=(b,t), n=(h,d)] -> [B,H,T,D]
                int b = m / T_, t = m - b*T_;
                int h = n / D_, d = n - h*D_;
                C[(((size_t)(b*H_ + h))*T_ + t)*D_ + d] = v;
            } else if (EPI == EPI_BIAS_RESID) {
                C[(size_t)m*N + n] = v + bias[n] + resid[(size_t)m*N + n];
            } else if (EPI == EPI_BIAS_GELU) {
                v += bias[n];
                float u = 0.7978845608028654f * (v + 0.044715f*v*v*v);
                C[(size_t)m*N + n] = 0.5f * v * (1.f + tanhf(u));
            } else {
                C[(size_t)m*N + n] = v;
            }
        }
    }
}

// ---------------- scores = Q K^T / 8, lower-triangular tiles only ----------------
__global__ void __launch_bounds__(256)
attn_scores(const float* __restrict__ Q, const float* __restrict__ Kv,
            float* __restrict__ S)
{
    const int ntile = blockIdx.x, mtile = blockIdx.y, bh = blockIdx.z;
    if (ntile > mtile) return;                 // fully-masked tile: skip
    const float* Qb = Q + (size_t)bh*T_*D_;
    const float* Kb = Kv + (size_t)bh*T_*D_;
    float* Sb = S + (size_t)bh*T_*T_;
    const int m0 = mtile*64, n0 = ntile*64;
    __shared__ float As[16][64], Bs[16][64];   // both [d][row] transposed
    const int tx = threadIdx.x & 15, ty = threadIdx.x >> 4;
    const int lr = threadIdx.x >> 2, lc = (threadIdx.x & 3) * 4;
    float acc[4][4] = {};
    for (int k0 = 0; k0 < D_; k0 += 16) {
        float4 av = *(const float4*)&Qb[(size_t)(m0 + lr)*D_ + k0 + lc];
        As[lc+0][lr] = av.x; As[lc+1][lr] = av.y; As[lc+2][lr] = av.z; As[lc+3][lr] = av.w;
        float4 bv = *(const float4*)&Kb[(size_t)(n0 + lr)*D_ + k0 + lc];
        Bs[lc+0][lr] = bv.x; Bs[lc+1][lr] = bv.y; Bs[lc+2][lr] = bv.z; Bs[lc+3][lr] = bv.w;
        __syncthreads();
        #pragma unroll
        for (int k = 0; k < 16; k++) {
            float4 a = *(const float4*)&As[k][ty*4];
            float4 b = *(const float4*)&Bs[k][tx*4];
            float ar[4] = {a.x,a.y,a.z,a.w}, brr[4] = {b.x,b.y,b.z,b.w};
            #pragma unroll
            for (int i = 0; i < 4; i++)
                #pragma unroll
                for (int j = 0; j < 4; j++) acc[i][j] += ar[i]*brr[j];
        }
        __syncthreads();
    }
    #pragma unroll
    for (int i = 0; i < 4; i++)
        #pragma unroll
        for (int j = 0; j < 4; j++)
            Sb[(size_t)(m0 + ty*4 + i)*T_ + n0 + tx*4 + j] = acc[i][j] * 0.125f;
}

// ---------------- causal softmax in-place on a row ----------------
__global__ void __launch_bounds__(256)
attn_softmax(float* __restrict__ S)
{
    const int q = blockIdx.x, bh = blockIdx.y;
    float* row = S + ((size_t)bh*T_ + q)*T_;
    const int len = q + 1;
    __shared__ float buf[T_];
    __shared__ float red[8];

    float mx = -1e30f;
    for (int i = threadIdx.x; i < len; i += 256) { float v = row[i]; buf[i] = v; mx = fmaxf(mx, v); }
    #pragma unroll
    for (int o = 16; o; o >>= 1) mx = fmaxf(mx, __shfl_xor_sync(0xffffffffu, mx, o));
    if ((threadIdx.x & 31) == 0) red[threadIdx.x>>5] = mx;
    __syncthreads();
    float m2 = -1e30f;
    #pragma unroll
    for (int i = 0; i < 8; i++) m2 = fmaxf(m2, red[i]);
    __syncthreads();

    float sum = 0.f;
    for (int i = threadIdx.x; i < len; i += 256) { float e = __expf(buf[i] - m2); buf[i] = e; sum += e; }
    #pragma unroll
    for (int o = 16; o; o >>= 1) sum += __shfl_xor_sync(0xffffffffu, sum, o);
    if ((threadIdx.x & 31) == 0) red[threadIdx.x>>5] = sum;
    __syncthreads();
    float ts = 0.f;
    #pragma unroll
    for (int i = 0; i < 8; i++) ts += red[i];
    float inv = 1.f / ts;

    for (int i = threadIdx.x; i < len; i += 256) row[i] = buf[i] * inv;
    const int zend = (q & ~63) + 64;          // zero-pad to tile edge for ctx GEMM
    for (int i = len + threadIdx.x; i < zend; i += 256) row[i] = 0.f;
}

// ---------------- ctx = P @ V  (K bounded by causality), writes [B,T,H,D] ----------------
__global__ void __launch_bounds__(256)
attn_ctx(const float* __restrict__ S, const float* __restrict__ V,
         float* __restrict__ ctx)
{
    const int mtile = blockIdx.x, bh = blockIdx.y;
    const float* Sb = S + (size_t)bh*T_*T_;
    const float* Vb = V + (size_t)bh*T_*D_;
    const int m0 = mtile*64;
    const int kmax = m0 + 64;                 // causal bound
    __shared__ float As[16][64], Bs[16][64];
    const int tx = threadIdx.x & 15, ty = threadIdx.x >> 4;
    const int lr = threadIdx.x >> 2, lc = (threadIdx.x & 3) * 4;
    const int br = threadIdx.x >> 4, bc = (threadIdx.x & 15) * 4;
    float acc[4][4] = {};
    for (int k0 = 0; k0 < kmax; k0 += 16) {
        float4 av = *(const float4*)&Sb[(size_t)(m0 + lr)*T_ + k0 + lc];
        As[lc+0][lr] = av.x; As[lc+1][lr] = av.y; As[lc+2][lr] = av.z; As[lc+3][lr] = av.w;
        *(float4*)&Bs[br][bc] = *(const float4*)&Vb[(size_t)(k0 + br)*D_ + bc];
        __syncthreads();
        #pragma unroll
        for (int k = 0; k < 16; k++) {
            float4 a = *(const float4*)&As[k][ty*4];
            float4 b = *(const float4*)&Bs[k][tx*4];
            float ar[4] = {a.x,a.y,a.z,a.w}, brr[4] = {b.x,b.y,b.z,b.w};
            #pragma unroll
            for (int i = 0; i < 4; i++)
                #pragma unroll
                for (int j = 0; j < 4; j++) acc[i][j] += ar[i]*brr[j];
        }
        __syncthreads();
    }
    const int b = bh / H_, h = bh - b*H_;
    #pragma unroll
    for (int i = 0; i < 4; i++) {
        int m = m0 + ty*4 + i;
        #pragma unroll
        for (int j = 0; j < 4; j++)
            ctx[((size_t)(b*T_ + m))*E_ + h*D_ + tx*4 + j] = acc[i][j];
    }
}

// ---------------- launch ----------------
extern "C" void kernel_launch(void* const* d_in, const int* in_sizes, int n_in,
                              void* d_out, int out_size)
{
    const float* x    = (const float*)d_in[0];
    const float* wq   = (const float*)d_in[1];
    const float* wk   = (const float*)d_in[2];
    const float* wv   = (const float*)d_in[3];
    const float* wo   = (const float*)d_in[4];
    const float* bo   = (const float*)d_in[5];
    const float* ln1s = (const float*)d_in[6];
    const float* ln1b = (const float*)d_in[7];
    const float* ln2s = (const float*)d_in[8];
    const float* ln2b = (const float*)d_in[9];
    const float* w1   = (const float*)d_in[10];
    const float* b1   = (const float*)d_in[11];
    const float* w2   = (const float*)d_in[12];
    const float* b2   = (const float*)d_in[13];
    float* out = (float*)d_out;

    float *h1, *q, *k, *v, *s, *ctx, *x2, *h2, *mid;
    cudaGetSymbolAddress((void**)&h1,  g_h1);
    cudaGetSymbolAddress((void**)&q,   g_q);
    cudaGetSymbolAddress((void**)&k,   g_k);
    cudaGetSymbolAddress((void**)&v,   g_v);
    cudaGetSymbolAddress((void**)&s,   g_s);
    cudaGetSymbolAddress((void**)&ctx, g_ctx);
    cudaGetSymbolAddress((void**)&x2,  g_x2);
    cudaGetSymbolAddress((void**)&h2,  g_h2);
    cudaGetSymbolAddress((void**)&mid, g_mid);

    // LN1
    ln_kernel<<<M_, 256>>>(x, ln1s, ln1b, h1);

    // QKV projections -> [B,H,T,D]
    dim3 gEE(E_/64, M_/64);
    sgemm<EPI_QKV><<<gEE, 256>>>(h1, wq, nullptr, nullptr, q, M_, E_, E_);
    sgemm<EPI_QKV><<<gEE, 256>>>(h1, wk, nullptr, nullptr, k, M_, E_, E_);
    sgemm<EPI_QKV><<<gEE, 256>>>(h1, wv, nullptr, nullptr, v, M_, E_, E_);

    // attention
    attn_scores<<<dim3(T_/64, T_/64, BH_), 256>>>(q, k, s);
    attn_softmax<<<dim3(T_, BH_), 256>>>(s);
    attn_ctx<<<dim3(T_/64, BH_), 256>>>(s, v, ctx);

    // output projection + bias + residual
    sgemm<EPI_BIAS_RESID><<<gEE, 256>>>(ctx, wo, bo, x, x2, M_, E_, E_);

    // LN2
    ln_kernel<<<M_, 256>>>(x2, ln2s, ln2b, h2);

    // MLP
    sgemm<EPI_BIAS_GELU><<<dim3(FF_/64, M_/64), 256>>>(h2, w1, b1, nullptr, mid, M_, FF_, E_);
    sgemm<EPI_BIAS_RESID><<<gEE, 256>>>(mid, w2, b2, x2, out, M_, E_, FF_);
}

// round 2
// speedup vs baseline: 1.2094x; 1.2094x over previous
#include <cuda_runtime.h>
#include <math.h>

#define B_  2
#define T_  2048
#define E_  768
#define H_  12
#define D_  64
#define M_  (B_*T_)    // 4096 rows
#define FF_ (4*E_)     // 3072
#define BH_ (B_*H_)    // 24

// ---------------- scratch ----------------
__device__ float g_h1 [M_*E_];
__device__ float g_q  [M_*E_];                    // [B,H,T,D]
__device__ float g_k  [M_*E_];
__device__ float g_v  [M_*E_];
__device__ float g_ctx[M_*E_];                    // [B,T,E]
__device__ float g_x2 [M_*E_];
__device__ float g_h2 [M_*E_];
__device__ float g_mid[M_*FF_];

// ---------------- f32x2 helpers ----------------
__device__ __forceinline__ void fma2(unsigned long long &acc, unsigned long long a, unsigned long long b) {
    asm("fma.rn.f32x2 %0, %1, %2, %0;" : "+l"(acc) : "l"(a), "l"(b));
}
__device__ __forceinline__ unsigned long long mul2(unsigned long long a, unsigned long long b) {
    unsigned long long r;
    asm("mul.rn.f32x2 %0, %1, %2;" : "=l"(r) : "l"(a), "l"(b));
    return r;
}
__device__ __forceinline__ unsigned long long dup2(float a) {
    unsigned long long r;
    asm("mov.b64 %0, {%1, %1};" : "=l"(r) : "f"(a));
    return r;
}
__device__ __forceinline__ float2 u2f(unsigned long long v) {
    float2 f;
    asm("mov.b64 {%0, %1}, %2;" : "=f"(f.x), "=f"(f.y) : "l"(v));
    return f;
}

// ---------------- LayerNorm (ddof=1) ----------------
__global__ void __launch_bounds__(256)
ln_kernel(const float* __restrict__ x, const float* __restrict__ sc,
          const float* __restrict__ sh, float* __restrict__ out)
{
    int row = blockIdx.x;
    const float* xr = x + (size_t)row * E_;
    float s = 0.f, s2 = 0.f;
    for (int i = threadIdx.x; i < E_; i += 256) { float v = xr[i]; s += v; s2 += v*v; }
    __shared__ float rs[8], rs2[8];
    #pragma unroll
    for (int o = 16; o; o >>= 1) {
        s  += __shfl_xor_sync(0xffffffffu, s,  o);
        s2 += __shfl_xor_sync(0xffffffffu, s2, o);
    }
    if ((threadIdx.x & 31) == 0) { rs[threadIdx.x>>5] = s; rs2[threadIdx.x>>5] = s2; }
    __syncthreads();
    float ts = 0.f, ts2 = 0.f;
    #pragma unroll
    for (int i = 0; i < 8; i++) { ts += rs[i]; ts2 += rs2[i]; }
    float mean = ts * (1.f / E_);
    float var  = (ts2 - ts * mean) * (1.f / (E_ - 1));
    float rstd = rsqrtf(var + 1e-5f);
    float* outr = out + (size_t)row * E_;
    for (int i = threadIdx.x; i < E_; i += 256)
        outr[i] = sc[i] * (xr[i] - mean) * rstd + sh[i];
}

// ---------------- SGEMM v2: 128x128 tile, 8x8 micro, f32x2, double-buffered ----------------
enum { EPI_NONE = 0, EPI_QKV = 1, EPI_BIAS_RESID = 2, EPI_BIAS_GELU = 3 };

template<int EPI>
__global__ void __launch_bounds__(256, 2)
sgemm(const float* __restrict__ A, const float* __restrict__ Bm,
      const float* __restrict__ bias, const float* __restrict__ resid,
      float* __restrict__ C, int M, int N, int K)
{
    __shared__ float As[2][16][128];   // [buf][k][m]
    __shared__ float Bs[2][16][128];   // [buf][k][n]
    const int tid = threadIdx.x;
    const int m0 = blockIdx.y * 128, n0 = blockIdx.x * 128;
    const int tx = tid & 15, ty = tid >> 4;
    const int ar = tid & 127;            // A row
    const int ak = (tid >> 7) * 8;       // A k-offset 0/8
    const int bk = tid >> 4;             // B k row
    const int bn = (tid & 15) * 4;       // B col chunk

    unsigned long long acc[8][4] = {};   // 8 rows x 4 col-pairs

    // prefetch tile 0
    float4 a0 = *(const float4*)&A[(size_t)(m0 + ar) * K + ak];
    float4 a1 = *(const float4*)&A[(size_t)(m0 + ar) * K + ak + 4];
    float4 b0 = *(const float4*)&Bm[(size_t)bk * N + n0 + bn];
    float4 b1 = *(const float4*)&Bm[(size_t)bk * N + n0 + bn + 64];
    As[0][ak+0][ar] = a0.x; As[0][ak+1][ar] = a0.y; As[0][ak+2][ar] = a0.z; As[0][ak+3][ar] = a0.w;
    As[0][ak+4][ar] = a1.x; As[0][ak+5][ar] = a1.y; As[0][ak+6][ar] = a1.z; As[0][ak+7][ar] = a1.w;
    *(float4*)&Bs[0][bk][bn]      = b0;
    *(float4*)&Bs[0][bk][bn + 64] = b1;
    __syncthreads();

    const int NK = K >> 4;
    for (int kt = 0; kt < NK; ++kt) {
        const int cur = kt & 1;
        if (kt + 1 < NK) {
            const float* Ap = &A[(size_t)(m0 + ar) * K + (kt + 1) * 16 + ak];
            a0 = *(const float4*)Ap;
            a1 = *(const float4*)(Ap + 4);
            const float* Bp = &Bm[(size_t)((kt + 1) * 16 + bk) * N + n0 + bn];
            b0 = *(const float4*)Bp;
            b1 = *(const float4*)(Bp + 64);
        }
        #pragma unroll
        for (int k = 0; k < 16; ++k) {
            float4 af0 = *(const float4*)&As[cur][k][ty * 4];
            float4 af1 = *(const float4*)&As[cur][k][64 + ty * 4];
            ulonglong2 bv0 = *(const ulonglong2*)&Bs[cur][k][tx * 4];
            ulonglong2 bv1 = *(const ulonglong2*)&Bs[cur][k][64 + tx * 4];
            float av[8] = {af0.x, af0.y, af0.z, af0.w, af1.x, af1.y, af1.z, af1.w};
            #pragma unroll
            for (int i = 0; i < 8; i++) {
                unsigned long long ad = dup2(av[i]);
                fma2(acc[i][0], ad, bv0.x);
                fma2(acc[i][1], ad, bv0.y);
                fma2(acc[i][2], ad, bv1.x);
                fma2(acc[i][3], ad, bv1.y);
            }
        }
        if (kt + 1 < NK) {
            const int nxt = cur ^ 1;
            As[nxt][ak+0][ar] = a0.x; As[nxt][ak+1][ar] = a0.y; As[nxt][ak+2][ar] = a0.z; As[nxt][ak+3][ar] = a0.w;
            As[nxt][ak+4][ar] = a1.x; As[nxt][ak+5][ar] = a1.y; As[nxt][ak+6][ar] = a1.z; As[nxt][ak+7][ar] = a1.w;
            *(float4*)&Bs[nxt][bk][bn]      = b0;
            *(float4*)&Bs[nxt][bk][bn + 64] = b1;
        }
        __syncthreads();
    }

    #pragma unroll
    for (int i = 0; i < 8; i++) {
        const int m = m0 + ((i < 4) ? (ty * 4 + i) : (64 + ty * 4 + i - 4));
        #pragma unroll
        for (int cp = 0; cp < 4; cp++) {
            float2 f = u2f(acc[i][cp]);
            float vv[2] = {f.x, f.y};
            #pragma unroll
            for (int hh = 0; hh < 2; hh++) {
                const int n = n0 + (cp >> 1) * 64 + tx * 4 + (cp & 1) * 2 + hh;
                float v = vv[hh];
                if (EPI == EPI_QKV) {
                    int b = m / T_, t = m - b * T_;
                    int h = n >> 6, d = n & 63;
                    C[(((size_t)(b * H_ + h)) * T_ + t) * D_ + d] = v;
                } else if (EPI == EPI_BIAS_RESID) {
                    C[(size_t)m * N + n] = v + bias[n] + resid[(size_t)m * N + n];
                } else if (EPI == EPI_BIAS_GELU) {
                    v += bias[n];
                    float u = 0.7978845608028654f * (v + 0.044715f * v * v * v);
                    C[(size_t)m * N + n] = 0.5f * v * (1.f + tanhf(u));
                } else {
                    C[(size_t)m * N + n] = v;
                }
            }
        }
    }
}

// ---------------- fused flash attention: 64q x 64kv tiles ----------------
// dyn smem layout: Qs[64][64], Ks[64][64], Vs[64][68], Ps[64][68]
#define FA_QS   0
#define FA_KS   (64*64)
#define FA_VS   (2*64*64)
#define FA_PS   (2*64*64 + 64*68)
#define FA_SMEM ((2*64*64 + 2*64*68) * 4)

__global__ void __launch_bounds__(256)
flash_attn(const float* __restrict__ Qp, const float* __restrict__ Kp,
           const float* __restrict__ Vp, float* __restrict__ ctx)
{
    extern __shared__ float sm[];
    float* Qs = sm + FA_QS;   // [d][q]  stride 64
    float* Ks = sm + FA_KS;   // [d][kv] stride 64
    float* Vs = sm + FA_VS;   // [kv][d] stride 68
    float* Ps = sm + FA_PS;   // [q][kv] stride 68

    const int tid = threadIdx.x;
    const int bh = blockIdx.y;
    const int mtile = (gridDim.x - 1) - blockIdx.x;   // heavy tiles first
    const int q0 = mtile * 64;
    const int tx = tid & 15, ty = tid >> 4;
    const int lr = tid & 63;            // row for loaders
    const int lc = (tid >> 6) * 16;     // 16-col chunk

    const float* Qb = Qp + (size_t)bh * T_ * D_;
    const float* Kb = Kp + (size_t)bh * T_ * D_;
    const float* Vb = Vp + (size_t)bh * T_ * D_;

    // load Q tile (transposed: Qs[d][q])
    #pragma unroll
    for (int u = 0; u < 4; u++) {
        float4 f = *(const float4*)&Qb[(size_t)(q0 + lr) * D_ + lc + 4 * u];
        Qs[(lc + 4*u + 0) * 64 + lr] = f.x;
        Qs[(lc + 4*u + 1) * 64 + lr] = f.y;
        Qs[(lc + 4*u + 2) * 64 + lr] = f.z;
        Qs[(lc + 4*u + 3) * 64 + lr] = f.w;
    }

    float mrun[4] = {-1e30f, -1e30f, -1e30f, -1e30f};
    float lrun[4] = {0.f, 0.f, 0.f, 0.f};
    unsigned long long cacc[4][2] = {};   // ctx acc: rows ty*4+i, col pairs

    for (int kt = 0; kt <= mtile; kt++) {
        const int kv0 = kt * 64;
        // load K (transposed) and V (straight)
        #pragma unroll
        for (int u = 0; u < 4; u++) {
            float4 f = *(const float4*)&Kb[(size_t)(kv0 + lr) * D_ + lc + 4 * u];
            Ks[(lc + 4*u + 0) * 64 + lr] = f.x;
            Ks[(lc + 4*u + 1) * 64 + lr] = f.y;
            Ks[(lc + 4*u + 2) * 64 + lr] = f.z;
            Ks[(lc + 4*u + 3) * 64 + lr] = f.w;
            float4 g = *(const float4*)&Vb[(size_t)(kv0 + lr) * D_ + lc + 4 * u];
            *(float4*)&Vs[lr * 68 + lc + 4 * u] = g;
        }
        __syncthreads();

        // S = Q @ K^T  (reduce over d)
        unsigned long long sacc[4][2] = {};
        #pragma unroll 8
        for (int k = 0; k < 64; k++) {
            float4 af = *(const float4*)&Qs[k * 64 + ty * 4];
            ulonglong2 bv = *(const ulonglong2*)&Ks[k * 64 + tx * 4];
            float av[4] = {af.x, af.y, af.z, af.w};
            #pragma unroll
            for (int i = 0; i < 4; i++) {
                unsigned long long ad = dup2(av[i]);
                fma2(sacc[i][0], ad, bv.x);
                fma2(sacc[i][1], ad, bv.y);
            }
        }

        // online softmax
        const bool diag = (kt == mtile);
        #pragma unroll
        for (int i = 0; i < 4; i++) {
            float2 f0 = u2f(sacc[i][0]);
            float2 f1 = u2f(sacc[i][1]);
            float s_[4] = {f0.x * 0.125f, f0.y * 0.125f, f1.x * 0.125f, f1.y * 0.125f};
            if (diag) {
                #pragma unroll
                for (int j = 0; j < 4; j++)
                    if (ty * 4 + i < tx * 4 + j) s_[j] = -1e30f;
            }
            float mx = fmaxf(fmaxf(s_[0], s_[1]), fmaxf(s_[2], s_[3]));
            #pragma unroll
            for (int o = 1; o < 16; o <<= 1) mx = fmaxf(mx, __shfl_xor_sync(0xffffffffu, mx, o));
            float mnew = fmaxf(mrun[i], mx);
            float corr = __expf(mrun[i] - mnew);
            float p0 = __expf(s_[0] - mnew), p1 = __expf(s_[1] - mnew);
            float p2 = __expf(s_[2] - mnew), p3 = __expf(s_[3] - mnew);
            float psum = p0 + p1 + p2 + p3;
            #pragma unroll
            for (int o = 1; o < 16; o <<= 1) psum += __shfl_xor_sync(0xffffffffu, psum, o);
            lrun[i] = lrun[i] * corr + psum;
            mrun[i] = mnew;
            unsigned long long cd = dup2(corr);
            cacc[i][0] = mul2(cacc[i][0], cd);
            cacc[i][1] = mul2(cacc[i][1], cd);
            *(float4*)&Ps[(ty * 4 + i) * 68 + tx * 4] = make_float4(p0, p1, p2, p3);
        }
        __syncthreads();

        // ctx += P @ V  (reduce over kv)
        #pragma unroll 4
        for (int k0 = 0; k0 < 64; k0 += 4) {
            float4 a4[4];
            #pragma unroll
            for (int i = 0; i < 4; i++)
                a4[i] = *(const float4*)&Ps[(ty * 4 + i) * 68 + k0];
            #pragma unroll
            for (int kk = 0; kk < 4; kk++) {
                ulonglong2 bv = *(const ulonglong2*)&Vs[(k0 + kk) * 68 + tx * 4];
                #pragma unroll
                for (int i = 0; i < 4; i++) {
                    float aa[4] = {a4[i].x, a4[i].y, a4[i].z, a4[i].w};
                    unsigned long long ad = dup2(aa[kk]);
                    fma2(cacc[i][0], ad, bv.x);
                    fma2(cacc[i][1], ad, bv.y);
                }
            }
        }
        __syncthreads();
    }

    // write out: ctx[b, q, h*64 + d]
    const int b = bh / H_, h = bh - b * H_;
    #pragma unroll
    for (int i = 0; i < 4; i++) {
        float inv = 1.f / lrun[i];
        int row = q0 + ty * 4 + i;
        float2 c0 = u2f(cacc[i][0]);
        float2 c1 = u2f(cacc[i][1]);
        float4 o = make_float4(c0.x * inv, c0.y * inv, c1.x * inv, c1.y * inv);
        *(float4*)&ctx[((size_t)(b * T_ + row)) * E_ + h * D_ + tx * 4] = o;
    }
}

// ---------------- launch ----------------
extern "C" void kernel_launch(void* const* d_in, const int* in_sizes, int n_in,
                              void* d_out, int out_size)
{
    const float* x    = (const float*)d_in[0];
    const float* wq   = (const float*)d_in[1];
    const float* wk   = (const float*)d_in[2];
    const float* wv   = (const float*)d_in[3];
    const float* wo   = (const float*)d_in[4];
    const float* bo   = (const float*)d_in[5];
    const float* ln1s = (const float*)d_in[6];
    const float* ln1b = (const float*)d_in[7];
    const float* ln2s = (const float*)d_in[8];
    const float* ln2b = (const float*)d_in[9];
    const float* w1   = (const float*)d_in[10];
    const float* b1   = (const float*)d_in[11];
    const float* w2   = (const float*)d_in[12];
    const float* b2   = (const float*)d_in[13];
    float* out = (float*)d_out;

    float *h1, *q, *k, *v, *ctx, *x2, *h2, *mid;
    cudaGetSymbolAddress((void**)&h1,  g_h1);
    cudaGetSymbolAddress((void**)&q,   g_q);
    cudaGetSymbolAddress((void**)&k,   g_k);
    cudaGetSymbolAddress((void**)&v,   g_v);
    cudaGetSymbolAddress((void**)&ctx, g_ctx);
    cudaGetSymbolAddress((void**)&x2,  g_x2);
    cudaGetSymbolAddress((void**)&h2,  g_h2);
    cudaGetSymbolAddress((void**)&mid, g_mid);

    cudaFuncSetAttribute(flash_attn, cudaFuncAttributeMaxDynamicSharedMemorySize, FA_SMEM);

    // LN1
    ln_kernel<<<M_, 256>>>(x, ln1s, ln1b, h1);

    // QKV projections -> [B,H,T,D]
    dim3 gEE(E_/128, M_/128);
    sgemm<EPI_QKV><<<gEE, 256>>>(h1, wq, nullptr, nullptr, q, M_, E_, E_);
    sgemm<EPI_QKV><<<gEE, 256>>>(h1, wk, nullptr, nullptr, k, M_, E_, E_);
    sgemm<EPI_QKV><<<gEE, 256>>>(h1, wv, nullptr, nullptr, v, M_, E_, E_);

    // fused attention
    flash_attn<<<dim3(T_/64, BH_), 256, FA_SMEM>>>(q, k, v, ctx);

    // output projection + bias + residual
    sgemm<EPI_BIAS_RESID><<<gEE, 256>>>(ctx, wo, bo, x, x2, M_, E_, E_);

    // LN2
    ln_kernel<<<M_, 256>>>(x2, ln2s, ln2b, h2);

    // MLP
    sgemm<EPI_BIAS_GELU><<<dim3(FF_/128, M_/128), 256>>>(h2, w1, b1, nullptr, mid, M_, FF_, E_);
    sgemm<EPI_BIAS_RESID><<<gEE, 256>>>(mid, w2, b2, x2, out, M_, E_, FF_);
}

// round 4
// speedup vs baseline: 2.2090x; 1.8265x over previous
#include <cuda_runtime.h>
#include <cuda_bf16.h>
#include <math.h>
#include <cstdint>

#define B_  2
#define T_  2048
#define E_  768
#define H_  12
#define D_  64
#define M_  (B_*T_)    // 4096
#define FF_ (4*E_)     // 3072
#define BH_ (B_*H_)    // 24
#define QKVN (3*E_)    // 2304

typedef __nv_bfloat16 bf16;

// ---------------- scratch ----------------
__device__ float g_q [M_*E_], g_k [M_*E_], g_v [M_*E_], g_x2[M_*E_];
__device__ bf16 g_h1h[M_*E_],  g_h1l[M_*E_];
__device__ bf16 g_ctxh[M_*E_], g_ctxl[M_*E_];
__device__ bf16 g_h2h[M_*E_],  g_h2l[M_*E_];
__device__ bf16 g_midh[(size_t)M_*FF_], g_midl[(size_t)M_*FF_];
__device__ bf16 g_wqkvTh[(size_t)QKVN*E_], g_wqkvTl[(size_t)QKVN*E_];  // [2304,768]
__device__ bf16 g_woTh[E_*E_], g_woTl[E_*E_];
__device__ bf16 g_w1Th[(size_t)E_*FF_], g_w1Tl[(size_t)E_*FF_];        // [3072,768]
__device__ bf16 g_w2Th[(size_t)E_*FF_], g_w2Tl[(size_t)E_*FF_];        // [768,3072]

// ---------------- helpers ----------------
__device__ __forceinline__ uint32_t smem_u32(const void* p) {
    uint32_t a;
    asm("{ .reg .u64 t; cvta.to.shared.u64 t, %1; cvt.u32.u64 %0, t; }" : "=r"(a) : "l"(p));
    return a;
}
__device__ __forceinline__ void cpasync16(uint32_t dst, const void* src) {
    asm volatile("cp.async.ca.shared.global [%0], [%1], 16;" :: "r"(dst), "l"(src));
}
__device__ __forceinline__ void ldsm4(uint32_t* r, uint32_t addr) {
    asm volatile("ldmatrix.sync.aligned.m8n8.x4.shared.b16 {%0,%1,%2,%3}, [%4];"
        : "=r"(r[0]), "=r"(r[1]), "=r"(r[2]), "=r"(r[3]) : "r"(addr));
}
__device__ __forceinline__ void mma_bf16(float* c, const uint32_t* a, uint32_t b0, uint32_t b1) {
    asm volatile("mma.sync.aligned.m16n8k16.row.col.f32.bf16.bf16.f32 "
        "{%0,%1,%2,%3}, {%4,%5,%6,%7}, {%8,%9}, {%0,%1,%2,%3};"
        : "+f"(c[0]), "+f"(c[1]), "+f"(c[2]), "+f"(c[3])
        : "r"(a[0]), "r"(a[1]), "r"(a[2]), "r"(a[3]), "r"(b0), "r"(b1));
}
__device__ __forceinline__ void fma2(unsigned long long &acc, unsigned long long a, unsigned long long b) {
    asm("fma.rn.f32x2 %0, %1, %2, %0;" : "+l"(acc) : "l"(a), "l"(b));
}
__device__ __forceinline__ unsigned long long mul2(unsigned long long a, unsigned long long b) {
    unsigned long long r; asm("mul.rn.f32x2 %0, %1, %2;" : "=l"(r) : "l"(a), "l"(b)); return r;
}
__device__ __forceinline__ unsigned long long dup2(float a) {
    unsigned long long r; asm("mov.b64 %0, {%1, %1};" : "=l"(r) : "f"(a)); return r;
}
__device__ __forceinline__ float2 u2f(unsigned long long v) {
    float2 f; asm("mov.b64 {%0, %1}, %2;" : "=f"(f.x), "=f"(f.y) : "l"(v)); return f;
}
__device__ __forceinline__ void split_bf16(float v, bf16& h, bf16& l) {
    h = __float2bfloat16(v);
    l = __float2bfloat16(v - __bfloat162float(h));
}

// ---------------- weight transpose + split: w[K,N] -> wT hi/lo [N,K] ----------------
__global__ void __launch_bounds__(256)
wsplitT(const float* __restrict__ w, bf16* __restrict__ hi, bf16* __restrict__ lo, int K, int N)
{
    __shared__ float t[32][33];
    const int tx = threadIdx.x & 31, ty = threadIdx.x >> 5;
    const int n0 = blockIdx.x * 32, k0 = blockIdx.y * 32;
    #pragma unroll
    for (int i = 0; i < 32; i += 8)
        t[ty + i][tx] = w[(size_t)(k0 + ty + i) * N + n0 + tx];
    __syncthreads();
    #pragma unroll
    for (int i = 0; i < 32; i += 8) {
        float v = t[tx][ty + i];
        bf16 h, l; split_bf16(v, h, l);
        size_t o = (size_t)(n0 + ty + i) * K + k0 + tx;
        hi[o] = h; lo[o] = l;
    }
}

// ---------------- LayerNorm (ddof=1) -> bf16 hi/lo ----------------
__global__ void __launch_bounds__(256)
ln_kernel(const float* __restrict__ x, const float* __restrict__ sc,
          const float* __restrict__ sh, bf16* __restrict__ ohi, bf16* __restrict__ olo)
{
    int row = blockIdx.x;
    const float* xr = x + (size_t)row * E_;
    float s = 0.f, s2 = 0.f;
    for (int i = threadIdx.x; i < E_; i += 256) { float v = xr[i]; s += v; s2 += v * v; }
    __shared__ float rs[8], rs2[8];
    #pragma unroll
    for (int o = 16; o; o >>= 1) {
        s  += __shfl_xor_sync(0xffffffffu, s,  o);
        s2 += __shfl_xor_sync(0xffffffffu, s2, o);
    }
    if ((threadIdx.x & 31) == 0) { rs[threadIdx.x >> 5] = s; rs2[threadIdx.x >> 5] = s2; }
    __syncthreads();
    float ts = 0.f, ts2 = 0.f;
    #pragma unroll
    for (int i = 0; i < 8; i++) { ts += rs[i]; ts2 += rs2[i]; }
    float mean = ts * (1.f / E_);
    float var  = (ts2 - ts * mean) * (1.f / (E_ - 1));
    float rstd = rsqrtf(var + 1e-5f);
    for (int i = threadIdx.x; i < E_; i += 256) {
        float v = sc[i] * (xr[i] - mean) * rstd + sh[i];
        bf16 h, l; split_bf16(v, h, l);
        ohi[(size_t)row * E_ + i] = h;
        olo[(size_t)row * E_ + i] = l;
    }
}

// ---------------- warp-MMA GEMM: C[M,N] = A[M,K] * B^T (B stored [N,K]) ----------------
// hi/lo split: D = Ah*Bh + Ah*Bl + Al*Bh. 128x128 tile, 8 warps (64x32 each),
// K-chunk 64, cp.async double-buffered, 144B-padded smem rows (conflict-free ldmatrix).
enum { EPI_QKV = 0, EPI_BIAS_RESID = 1, EPI_BIAS_GELU_SPLIT = 2 };

#define KCH     64
#define ROWB    144
#define TILE_B  (128*ROWB)      // 18432
#define STAGE_B (4*TILE_B)      // 73728
#define GEMM_SMEM (2*STAGE_B)   // 147456

template<int EPI>
__global__ void __launch_bounds__(256, 1)
mma_gemm(const bf16* __restrict__ Ahi, const bf16* __restrict__ Alo,
         const bf16* __restrict__ Bhi, const bf16* __restrict__ Blo,
         const float* __restrict__ bias, const float* __restrict__ resid,
         float* __restrict__ C, float* __restrict__ Qo, float* __restrict__ Ko,
         float* __restrict__ Vo, bf16* __restrict__ Chi, bf16* __restrict__ Clo,
         int N, int K)
{
    extern __shared__ char sm[];
    const uint32_t sbase = smem_u32(sm);
    const int tid = threadIdx.x, wid = tid >> 5, lid = tid & 31;
    const int m0 = blockIdx.y * 128, n0 = blockIdx.x * 128;
    const int wm = wid >> 2, wn = wid & 3;      // 2x4 warp grid

    const int lrow = tid >> 3;                  // loader row 0..31
    const int lcb  = (tid & 7) * 16;            // loader col bytes

    float acc[4][4][4] = {};                    // [mt][nt][reg]

    const bf16* gs[4] = {Ahi, Alo, Bhi, Blo};
    const int   r0s[4] = {m0, m0, n0, n0};

    auto issue = [&](int c) {
        const int k0 = c * KCH;
        const uint32_t sb = sbase + (uint32_t)(c & 1) * STAGE_B;
        #pragma unroll
        for (int t = 0; t < 4; t++) {
            const char* g = (const char*)(gs[t] + (size_t)(r0s[t] + lrow) * K + k0) + lcb;
            uint32_t d = sb + t * TILE_B + lrow * ROWB + lcb;
            #pragma unroll
            for (int i = 0; i < 4; i++)
                cpasync16(d + i * 32 * ROWB, g + (size_t)i * 32 * K * 2);
        }
        asm volatile("cp.async.commit_group;");
    };

    const int NC = K / KCH;
    issue(0);

    // per-warp ldmatrix base offsets (within-tile)
    const int am = (lid >> 3);                  // matrix index 0..3
    const uint32_t aRow = wm * 64 + (am & 1) * 8 + (lid & 7);
    const uint32_t aColH = (am >> 1) * 16;
    const uint32_t bRowBase = wn * 32 + (lid & 7);
    const uint32_t bNt = (am >> 1);             // nt-within-pair
    const uint32_t bColH = (am & 1) * 16;

    for (int c = 0; c < NC; c++) {
        if (c + 1 < NC) { issue(c + 1); asm volatile("cp.async.wait_group 1;"); }
        else            { asm volatile("cp.async.wait_group 0;"); }
        __syncthreads();

        const uint32_t sb = sbase + (uint32_t)(c & 1) * STAGE_B;
        const uint32_t aHiB = sb,               aLoB = sb + TILE_B;
        const uint32_t bHiB = sb + 2 * TILE_B,  bLoB = sb + 3 * TILE_B;

        #pragma unroll
        for (int ks = 0; ks < 4; ks++) {
            // B fragments: 2 pairs x {hi,lo}
            uint32_t bh[2][4], bl[2][4];
            #pragma unroll
            for (int p = 0; p < 2; p++) {
                uint32_t row = bRowBase + (p * 2 + bNt) * 8;
                uint32_t off = row * ROWB + ks * 32 + bColH;
                ldsm4(bh[p], bHiB + off);
                ldsm4(bl[p], bLoB + off);
            }
            #pragma unroll
            for (int mt = 0; mt < 4; mt++) {
                uint32_t ah[4], al[4];
                uint32_t off = (aRow + mt * 16) * ROWB + ks * 32 + aColH;
                ldsm4(ah, aHiB + off);
                ldsm4(al, aLoB + off);
                #pragma unroll
                for (int nt = 0; nt < 4; nt++) {
                    const int p = nt >> 1, q = (nt & 1) * 2;
                    mma_bf16(acc[mt][nt], ah, bh[p][q], bh[p][q + 1]);
                    mma_bf16(acc[mt][nt], ah, bl[p][q], bl[p][q + 1]);
                    mma_bf16(acc[mt][nt], al, bh[p][q], bh[p][q + 1]);
                }
            }
        }
        __syncthreads();
    }

    // epilogue: thread holds per tile (mt,nt): rows r, r+8; cols cc, cc+1
    #pragma unroll
    for (int mt = 0; mt < 4; mt++) {
        #pragma unroll
        for (int nt = 0; nt < 4; nt++) {
            const int r0 = m0 + wm * 64 + mt * 16 + (lid >> 2);
            const int cc = n0 + wn * 32 + nt * 8 + (lid & 3) * 2;
            #pragma unroll
            for (int hh = 0; hh < 2; hh++) {
                const int r = r0 + hh * 8;
                float v0 = acc[mt][nt][hh * 2], v1 = acc[mt][nt][hh * 2 + 1];
                if (EPI == EPI_QKV) {
                    const int bb = r >> 11, tt = r & (T_ - 1);
                    int which = (cc >= 2 * E_) ? 2 : (cc >= E_ ? 1 : 0);
                    int nn = cc - which * E_;
                    int hx = nn >> 6, d = nn & 63;
                    float* dst = (which == 0) ? Qo : (which == 1) ? Ko : Vo;
                    *(float2*)&dst[(((size_t)(bb * H_ + hx)) * T_ + tt) * D_ + d] = make_float2(v0, v1);
                } else if (EPI == EPI_BIAS_RESID) {
                    size_t o = (size_t)r * N + cc;
                    float2 bs = *(const float2*)&bias[cc];
                    float2 rs = *(const float2*)&resid[o];
                    *(float2*)&C[o] = make_float2(v0 + bs.x + rs.x, v1 + bs.y + rs.y);
                } else {
                    size_t o = (size_t)r * N + cc;
                    float2 bs = *(const float2*)&bias[cc];
                    float vv[2] = {v0 + bs.x, v1 + bs.y};
                    bf16 ph[2], pl[2];
                    #pragma unroll
                    for (int j = 0; j < 2; j++) {
                        float v = vv[j];
                        float u = 0.7978845608028654f * (v + 0.044715f * v * v * v);
                        v = 0.5f * v * (1.f + tanhf(u));
                        split_bf16(v, ph[j], pl[j]);
                    }
                    *(__nv_bfloat162*)&Chi[o] = __nv_bfloat162(ph[0], ph[1]);
                    *(__nv_bfloat162*)&Clo[o] = __nv_bfloat162(pl[0], pl[1]);
                }
            }
        }
    }
}

// ---------------- fused flash attention (fp32, f32x2), ctx -> bf16 hi/lo ----------------
#define FA_QS   0
#define FA_KS   (64*64)
#define FA_VS   (2*64*64)
#define FA_PS   (2*64*64 + 64*68)
#define FA_SMEM ((2*64*64 + 2*64*68) * 4)

__global__ void __launch_bounds__(256)
flash_attn(const float* __restrict__ Qp, const float* __restrict__ Kp,
           const float* __restrict__ Vp, bf16* __restrict__ ctxh, bf16* __restrict__ ctxl)
{
    extern __shared__ float smf[];
    float* Qs = smf + FA_QS;
    float* Ks = smf + FA_KS;
    float* Vs = smf + FA_VS;
    float* Ps = smf + FA_PS;

    const int tid = threadIdx.x;
    const int bh = blockIdx.y;
    const int mtile = (gridDim.x - 1) - blockIdx.x;
    const int q0 = mtile * 64;
    const int tx = tid & 15, ty = tid >> 4;
    const int lr = tid & 63;
    const int lc = (tid >> 6) * 16;

    const float* Qb = Qp + (size_t)bh * T_ * D_;
    const float* Kb = Kp + (size_t)bh * T_ * D_;
    const float* Vb = Vp + (size_t)bh * T_ * D_;

    #pragma unroll
    for (int u = 0; u < 4; u++) {
        float4 f = *(const float4*)&Qb[(size_t)(q0 + lr) * D_ + lc + 4 * u];
        Qs[(lc + 4*u + 0) * 64 + lr] = f.x;
        Qs[(lc + 4*u + 1) * 64 + lr] = f.y;
        Qs[(lc + 4*u + 2) * 64 + lr] = f.z;
        Qs[(lc + 4*u + 3) * 64 + lr] = f.w;
    }

    float mrun[4] = {-1e30f, -1e30f, -1e30f, -1e30f};
    float lrun[4] = {0.f, 0.f, 0.f, 0.f};
    unsigned long long cacc[4][2] = {};

    for (int kt = 0; kt <= mtile; kt++) {
        const int kv0 = kt * 64;
        #pragma unroll
        for (int u = 0; u < 4; u++) {
            float4 f = *(const float4*)&Kb[(size_t)(kv0 + lr) * D_ + lc + 4 * u];
            Ks[(lc + 4*u + 0) * 64 + lr] = f.x;
            Ks[(lc + 4*u + 1) * 64 + lr] = f.y;
            Ks[(lc + 4*u + 2) * 64 + lr] = f.z;
            Ks[(lc + 4*u + 3) * 64 + lr] = f.w;
            float4 g = *(const float4*)&Vb[(size_t)(kv0 + lr) * D_ + lc + 4 * u];
            *(float4*)&Vs[lr * 68 + lc + 4 * u] = g;
        }
        __syncthreads();

        unsigned long long sacc[4][2] = {};
        #pragma unroll 8
        for (int k = 0; k < 64; k++) {
            float4 af = *(const float4*)&Qs[k * 64 + ty * 4];
            ulonglong2 bv = *(const ulonglong2*)&Ks[k * 64 + tx * 4];
            float av[4] = {af.x, af.y, af.z, af.w};
            #pragma unroll
            for (int i = 0; i < 4; i++) {
                unsigned long long ad = dup2(av[i]);
                fma2(sacc[i][0], ad, bv.x);
                fma2(sacc[i][1], ad, bv.y);
            }
        }

        const bool diag = (kt == mtile);
        #pragma unroll
        for (int i = 0; i < 4; i++) {
            float2 f0 = u2f(sacc[i][0]);
            float2 f1 = u2f(sacc[i][1]);
            float s_[4] = {f0.x * 0.125f, f0.y * 0.125f, f1.x * 0.125f, f1.y * 0.125f};
            if (diag) {
                #pragma unroll
                for (int j = 0; j < 4; j++)
                    if (ty * 4 + i < tx * 4 + j) s_[j] = -1e30f;
            }
            float mx = fmaxf(fmaxf(s_[0], s_[1]), fmaxf(s_[2], s_[3]));
            #pragma unroll
            for (int o = 1; o < 16; o <<= 1) mx = fmaxf(mx, __shfl_xor_sync(0xffffffffu, mx, o));
            float mnew = fmaxf(mrun[i], mx);
            float corr = __expf(mrun[i] - mnew);
            float p0 = __expf(s_[0] - mnew), p1 = __expf(s_[1] - mnew);
            float p2 = __expf(s_[2] - mnew), p3 = __expf(s_[3] - mnew);
            float psum = p0 + p1 + p2 + p3;
            #pragma unroll
            for (int o = 1; o < 16; o <<= 1) psum += __shfl_xor_sync(0xffffffffu, psum, o);
            lrun[i] = lrun[i] * corr + psum;
            mrun[i] = mnew;
            unsigned long long cd = dup2(corr);
            cacc[i][0] = mul2(cacc[i][0], cd);
            cacc[i][1] = mul2(cacc[i][1], cd);
            *(float4*)&Ps[(ty * 4 + i) * 68 + tx * 4] = make_float4(p0, p1, p2, p3);
        }
        __syncthreads();

        #pragma unroll 4
        for (int k0 = 0; k0 < 64; k0 += 4) {
            float4 a4[4];
            #pragma unroll
            for (int i = 0; i < 4; i++)
                a4[i] = *(const float4*)&Ps[(ty * 4 + i) * 68 + k0];
            #pragma unroll
            for (int kk = 0; kk < 4; kk++) {
                ulonglong2 bv = *(const ulonglong2*)&Vs[(k0 + kk) * 68 + tx * 4];
                #pragma unroll
                for (int i = 0; i < 4; i++) {
                    float aa[4] = {a4[i].x, a4[i].y, a4[i].z, a4[i].w};
                    unsigned long long ad = dup2(aa[kk]);
                    fma2(cacc[i][0], ad, bv.x);
                    fma2(cacc[i][1], ad, bv.y);
                }
            }
        }
        __syncthreads();
    }

    const int b = bh / H_, h = bh - b * H_;
    #pragma unroll
    for (int i = 0; i < 4; i++) {
        float inv = 1.f / lrun[i];
        int row = q0 + ty * 4 + i;
        float2 c0 = u2f(cacc[i][0]);
        float2 c1 = u2f(cacc[i][1]);
        float vals[4] = {c0.x * inv, c0.y * inv, c1.x * inv, c1.y * inv};
        bf16 hh[4], ll[4];
        #pragma unroll
        for (int j = 0; j < 4; j++) split_bf16(vals[j], hh[j], ll[j]);
        size_t o = ((size_t)(b * T_ + row)) * E_ + h * D_ + tx * 4;
        *(__nv_bfloat162*)&ctxh[o]     = __nv_bfloat162(hh[0], hh[1]);
        *(__nv_bfloat162*)&ctxh[o + 2] = __nv_bfloat162(hh[2], hh[3]);
        *(__nv_bfloat162*)&ctxl[o]     = __nv_bfloat162(ll[0], ll[1]);
        *(__nv_bfloat162*)&ctxl[o + 2] = __nv_bfloat162(ll[2], ll[3]);
    }
}

// ---------------- launch ----------------
extern "C" void kernel_launch(void* const* d_in, const int* in_sizes, int n_in,
                              void* d_out, int out_size)
{
    const float* x    = (const float*)d_in[0];
    const float* wq   = (const float*)d_in[1];
    const float* wk   = (const float*)d_in[2];
    const float* wv   = (const float*)d_in[3];
    const float* wo   = (const float*)d_in[4];
    const float* bo   = (const float*)d_in[5];
    const float* ln1s = (const float*)d_in[6];
    const float* ln1b = (const float*)d_in[7];
    const float* ln2s = (const float*)d_in[8];
    const float* ln2b = (const float*)d_in[9];
    const float* w1   = (const float*)d_in[10];
    const float* b1   = (const float*)d_in[11];
    const float* w2   = (const float*)d_in[12];
    const float* b2   = (const float*)d_in[13];
    float* out = (float*)d_out;

    float *q, *k, *v, *x2;
    bf16 *h1h, *h1l, *ctxh, *ctxl, *h2h, *h2l, *midh, *midl;
    bf16 *wqkvTh, *wqkvTl, *woTh, *woTl, *w1Th, *w1Tl, *w2Th, *w2Tl;
    cudaGetSymbolAddress((void**)&q,   g_q);
    cudaGetSymbolAddress((void**)&k,   g_k);
    cudaGetSymbolAddress((void**)&v,   g_v);
    cudaGetSymbolAddress((void**)&x2,  g_x2);
    cudaGetSymbolAddress((void**)&h1h, g_h1h);  cudaGetSymbolAddress((void**)&h1l, g_h1l);
    cudaGetSymbolAddress((void**)&ctxh,g_ctxh); cudaGetSymbolAddress((void**)&ctxl,g_ctxl);
    cudaGetSymbolAddress((void**)&h2h, g_h2h);  cudaGetSymbolAddress((void**)&h2l, g_h2l);
    cudaGetSymbolAddress((void**)&midh,g_midh); cudaGetSymbolAddress((void**)&midl,g_midl);
    cudaGetSymbolAddress((void**)&wqkvTh,g_wqkvTh); cudaGetSymbolAddress((void**)&wqkvTl,g_wqkvTl);
    cudaGetSymbolAddress((void**)&woTh,g_woTh); cudaGetSymbolAddress((void**)&woTl,g_woTl);
    cudaGetSymbolAddress((void**)&w1Th,g_w1Th); cudaGetSymbolAddress((void**)&w1Tl,g_w1Tl);
    cudaGetSymbolAddress((void**)&w2Th,g_w2Th); cudaGetSymbolAddress((void**)&w2Tl,g_w2Tl);

    cudaFuncSetAttribute(flash_attn, cudaFuncAttributeMaxDynamicSharedMemorySize, FA_SMEM);
    cudaFuncSetAttribute(mma_gemm<EPI_QKV>,             cudaFuncAttributeMaxDynamicSharedMemorySize, GEMM_SMEM);
    cudaFuncSetAttribute(mma_gemm<EPI_BIAS_RESID>,      cudaFuncAttributeMaxDynamicSharedMemorySize, GEMM_SMEM);
    cudaFuncSetAttribute(mma_gemm<EPI_BIAS_GELU_SPLIT>, cudaFuncAttributeMaxDynamicSharedMemorySize, GEMM_SMEM);

    // weight transpose+split; wq/wk/wv stacked into [2304,768]
    wsplitT<<<dim3(E_/32,  E_/32), 256>>>(wq, wqkvTh,            wqkvTl,            E_, E_);
    wsplitT<<<dim3(E_/32,  E_/32), 256>>>(wk, wqkvTh + E_*E_,    wqkvTl + E_*E_,    E_, E_);
    wsplitT<<<dim3(E_/32,  E_/32), 256>>>(wv, wqkvTh + 2*E_*E_,  wqkvTl + 2*E_*E_,  E_, E_);
    wsplitT<<<dim3(E_/32,  E_/32), 256>>>(wo, woTh, woTl, E_, E_);
    wsplitT<<<dim3(FF_/32, E_/32), 256>>>(w1, w1Th, w1Tl, E_, FF_);
    wsplitT<<<dim3(E_/32, FF_/32), 256>>>(w2, w2Th, w2Tl, FF_, E_);

    // LN1 -> h1 hi/lo
    ln_kernel<<<M_, 256>>>(x, ln1s, ln1b, h1h, h1l);

    // fused QKV: [4096,768] x [2304,768]^T
    mma_gemm<EPI_QKV><<<dim3(QKVN/128, M_/128), 256, GEMM_SMEM>>>(
        h1h, h1l, wqkvTh, wqkvTl, nullptr, nullptr, nullptr, q, k, v, nullptr, nullptr, QKVN, E_);

    // attention -> ctx hi/lo
    flash_attn<<<dim3(T_/64, BH_), 256, FA_SMEM>>>(q, k, v, ctxh, ctxl);

    // proj + bias + resid -> x2
    mma_gemm<EPI_BIAS_RESID><<<dim3(E_/128, M_/128), 256, GEMM_SMEM>>>(
        ctxh, ctxl, woTh, woTl, bo, x, x2, nullptr, nullptr, nullptr, nullptr, nullptr, E_, E_);

    // LN2 -> h2 hi/lo
    ln_kernel<<<M_, 256>>>(x2, ln2s, ln2b, h2h, h2l);

    // MLP1 (gelu) -> mid hi/lo
    mma_gemm<EPI_BIAS_GELU_SPLIT><<<dim3(FF_/128, M_/128), 256, GEMM_SMEM>>>(
        h2h, h2l, w1Th, w1Tl, b1, nullptr, nullptr, nullptr, nullptr, nullptr, midh, midl, FF_, E_);

    // MLP2 + bias + resid -> out
    mma_gemm<EPI_BIAS_RESID><<<dim3(E_/128, M_/128), 256, GEMM_SMEM>>>(
        midh, midl, w2Th, w2Tl, b2, x2, out, nullptr, nullptr, nullptr, nullptr, nullptr, E_, FF_);
}

// round 5
// speedup vs baseline: 3.2309x; 1.4626x over previous
#include <cuda_runtime.h>
#include <cuda_bf16.h>
#include <math.h>
#include <cstdint>

#define B_  2
#define T_  2048
#define E_  768
#define H_  12
#define D_  64
#define M_  (B_*T_)    // 4096
#define FF_ (4*E_)     // 3072
#define BH_ (B_*H_)    // 24
#define QKVN (3*E_)    // 2304

typedef __nv_bfloat16 bf16;

// ---------------- scratch ----------------
__device__ float g_x2[M_*E_];
__device__ bf16 g_h1h[M_*E_],  g_h1l[M_*E_];
__device__ bf16 g_qh[M_*E_],  g_ql[M_*E_];     // [B,H,T,D]
__device__ bf16 g_kh[M_*E_],  g_kl[M_*E_];     // [B,H,T,D]
__device__ bf16 g_vth[M_*E_], g_vtl[M_*E_];    // [B,H,D,T]
__device__ bf16 g_ctxh[M_*E_], g_ctxl[M_*E_];
__device__ bf16 g_h2h[M_*E_],  g_h2l[M_*E_];
__device__ bf16 g_midh[(size_t)M_*FF_], g_midl[(size_t)M_*FF_];
__device__ bf16 g_wqkvTh[(size_t)QKVN*E_], g_wqkvTl[(size_t)QKVN*E_];
__device__ bf16 g_woTh[E_*E_], g_woTl[E_*E_];
__device__ bf16 g_w1Th[(size_t)E_*FF_], g_w1Tl[(size_t)E_*FF_];
__device__ bf16 g_w2Th[(size_t)E_*FF_], g_w2Tl[(size_t)E_*FF_];

// ---------------- helpers ----------------
__device__ __forceinline__ uint32_t smem_u32(const void* p) {
    uint32_t a;
    asm("{ .reg .u64 t; cvta.to.shared.u64 t, %1; cvt.u32.u64 %0, t; }" : "=r"(a) : "l"(p));
    return a;
}
__device__ __forceinline__ void cpasync16(uint32_t dst, const void* src) {
    asm volatile("cp.async.ca.shared.global [%0], [%1], 16;" :: "r"(dst), "l"(src));
}
__device__ __forceinline__ void ldsm4(uint32_t* r, uint32_t addr) {
    asm volatile("ldmatrix.sync.aligned.m8n8.x4.shared.b16 {%0,%1,%2,%3}, [%4];"
        : "=r"(r[0]), "=r"(r[1]), "=r"(r[2]), "=r"(r[3]) : "r"(addr));
}
__device__ __forceinline__ void mma_bf16(float* c, const uint32_t* a, uint32_t b0, uint32_t b1) {
    asm volatile("mma.sync.aligned.m16n8k16.row.col.f32.bf16.bf16.f32 "
        "{%0,%1,%2,%3}, {%4,%5,%6,%7}, {%8,%9}, {%0,%1,%2,%3};"
        : "+f"(c[0]), "+f"(c[1]), "+f"(c[2]), "+f"(c[3])
        : "r"(a[0]), "r"(a[1]), "r"(a[2]), "r"(a[3]), "r"(b0), "r"(b1));
}
__device__ __forceinline__ void split_bf16(float v, bf16& h, bf16& l) {
    h = __float2bfloat16(v);
    l = __float2bfloat16(v - __bfloat162float(h));
}
__device__ __forceinline__ uint32_t packbf(float a, float b) {
    __nv_bfloat162 t = __floats2bfloat162_rn(a, b);
    return *(uint32_t*)&t;
}

// ---------------- weight transpose + split ----------------
__global__ void __launch_bounds__(256)
wsplitT(const float* __restrict__ w, bf16* __restrict__ hi, bf16* __restrict__ lo, int K, int N)
{
    __shared__ float t[32][33];
    const int tx = threadIdx.x & 31, ty = threadIdx.x >> 5;
    const int n0 = blockIdx.x * 32, k0 = blockIdx.y * 32;
    #pragma unroll
    for (int i = 0; i < 32; i += 8)
        t[ty + i][tx] = w[(size_t)(k0 + ty + i) * N + n0 + tx];
    __syncthreads();
    #pragma unroll
    for (int i = 0; i < 32; i += 8) {
        float v = t[tx][ty + i];
        bf16 h, l; split_bf16(v, h, l);
        size_t o = (size_t)(n0 + ty + i) * K + k0 + tx;
        hi[o] = h; lo[o] = l;
    }
}

// ---------------- LayerNorm (ddof=1) -> bf16 hi/lo ----------------
__global__ void __launch_bounds__(256)
ln_kernel(const float* __restrict__ x, const float* __restrict__ sc,
          const float* __restrict__ sh, bf16* __restrict__ ohi, bf16* __restrict__ olo)
{
    int row = blockIdx.x;
    const float* xr = x + (size_t)row * E_;
    float s = 0.f, s2 = 0.f;
    for (int i = threadIdx.x; i < E_; i += 256) { float v = xr[i]; s += v; s2 += v * v; }
    __shared__ float rs[8], rs2[8];
    #pragma unroll
    for (int o = 16; o; o >>= 1) {
        s  += __shfl_xor_sync(0xffffffffu, s,  o);
        s2 += __shfl_xor_sync(0xffffffffu, s2, o);
    }
    if ((threadIdx.x & 31) == 0) { rs[threadIdx.x >> 5] = s; rs2[threadIdx.x >> 5] = s2; }
    __syncthreads();
    float ts = 0.f, ts2 = 0.f;
    #pragma unroll
    for (int i = 0; i < 8; i++) { ts += rs[i]; ts2 += rs2[i]; }
    float mean = ts * (1.f / E_);
    float var  = (ts2 - ts * mean) * (1.f / (E_ - 1));
    float rstd = rsqrtf(var + 1e-5f);
    for (int i = threadIdx.x; i < E_; i += 256) {
        float v = sc[i] * (xr[i] - mean) * rstd + sh[i];
        bf16 h, l; split_bf16(v, h, l);
        ohi[(size_t)row * E_ + i] = h;
        olo[(size_t)row * E_ + i] = l;
    }
}

// ---------------- warp-MMA GEMM (as R4, QKV epilogue -> bf16 hi/lo + Vt) ----------------
enum { EPI_QKV = 0, EPI_BIAS_RESID = 1, EPI_BIAS_GELU_SPLIT = 2 };

#define KCH     64
#define ROWB    144
#define TILE_B  (128*ROWB)
#define STAGE_B (4*TILE_B)
#define GEMM_SMEM (2*STAGE_B)

template<int EPI>
__global__ void __launch_bounds__(256, 1)
mma_gemm(const bf16* __restrict__ Ahi, const bf16* __restrict__ Alo,
         const bf16* __restrict__ Bhi, const bf16* __restrict__ Blo,
         const float* __restrict__ bias, const float* __restrict__ resid,
         float* __restrict__ C,
         bf16* __restrict__ Qh, bf16* __restrict__ Ql,
         bf16* __restrict__ Kh, bf16* __restrict__ Kl,
         bf16* __restrict__ Vth, bf16* __restrict__ Vtl,
         bf16* __restrict__ Chi, bf16* __restrict__ Clo,
         int N, int K)
{
    extern __shared__ char sm[];
    const uint32_t sbase = smem_u32(sm);
    const int tid = threadIdx.x, wid = tid >> 5, lid = tid & 31;
    const int m0 = blockIdx.y * 128, n0 = blockIdx.x * 128;
    const int wm = wid >> 2, wn = wid & 3;

    const int lrow = tid >> 3;
    const int lcb  = (tid & 7) * 16;

    float acc[4][4][4] = {};

    const bf16* gs[4] = {Ahi, Alo, Bhi, Blo};
    const int   r0s[4] = {m0, m0, n0, n0};

    auto issue = [&](int c) {
        const int k0 = c * KCH;
        const uint32_t sb = sbase + (uint32_t)(c & 1) * STAGE_B;
        #pragma unroll
        for (int t = 0; t < 4; t++) {
            const char* g = (const char*)(gs[t] + (size_t)(r0s[t] + lrow) * K + k0) + lcb;
            uint32_t d = sb + t * TILE_B + lrow * ROWB + lcb;
            #pragma unroll
            for (int i = 0; i < 4; i++)
                cpasync16(d + i * 32 * ROWB, g + (size_t)i * 32 * K * 2);
        }
        asm volatile("cp.async.commit_group;");
    };

    const int NC = K / KCH;
    issue(0);

    const int am = (lid >> 3);
    const uint32_t aRow = wm * 64 + (am & 1) * 8 + (lid & 7);
    const uint32_t aColH = (am >> 1) * 16;
    const uint32_t bRowBase = wn * 32 + (lid & 7);
    const uint32_t bNt = (am >> 1);
    const uint32_t bColH = (am & 1) * 16;

    for (int c = 0; c < NC; c++) {
        if (c + 1 < NC) { issue(c + 1); asm volatile("cp.async.wait_group 1;"); }
        else            { asm volatile("cp.async.wait_group 0;"); }
        __syncthreads();

        const uint32_t sb = sbase + (uint32_t)(c & 1) * STAGE_B;
        const uint32_t aHiB = sb,               aLoB = sb + TILE_B;
        const uint32_t bHiB = sb + 2 * TILE_B,  bLoB = sb + 3 * TILE_B;

        #pragma unroll
        for (int ks = 0; ks < 4; ks++) {
            uint32_t bh[2][4], bl[2][4];
            #pragma unroll
            for (int p = 0; p < 2; p++) {
                uint32_t row = bRowBase + (p * 2 + bNt) * 8;
                uint32_t off = row * ROWB + ks * 32 + bColH;
                ldsm4(bh[p], bHiB + off);
                ldsm4(bl[p], bLoB + off);
            }
            #pragma unroll
            for (int mt = 0; mt < 4; mt++) {
                uint32_t ah[4], al[4];
                uint32_t off = (aRow + mt * 16) * ROWB + ks * 32 + aColH;
                ldsm4(ah, aHiB + off);
                ldsm4(al, aLoB + off);
                #pragma unroll
                for (int nt = 0; nt < 4; nt++) {
                    const int p = nt >> 1, q = (nt & 1) * 2;
                    mma_bf16(acc[mt][nt], ah, bh[p][q], bh[p][q + 1]);
                    mma_bf16(acc[mt][nt], ah, bl[p][q], bl[p][q + 1]);
                    mma_bf16(acc[mt][nt], al, bh[p][q], bh[p][q + 1]);
                }
            }
        }
        __syncthreads();
    }

    #pragma unroll
    for (int mt = 0; mt < 4; mt++) {
        #pragma unroll
        for (int nt = 0; nt < 4; nt++) {
            const int r0 = m0 + wm * 64 + mt * 16 + (lid >> 2);
            const int cc = n0 + wn * 32 + nt * 8 + (lid & 3) * 2;
            #pragma unroll
            for (int hh = 0; hh < 2; hh++) {
                const int r = r0 + hh * 8;
                float v0 = acc[mt][nt][hh * 2], v1 = acc[mt][nt][hh * 2 + 1];
                if (EPI == EPI_QKV) {
                    const int bb = r >> 11, tt = r & (T_ - 1);
                    int which = (cc >= 2 * E_) ? 2 : (cc >= E_ ? 1 : 0);
                    int nn = cc - which * E_;
                    int hx = nn >> 6, d = nn & 63;
                    bf16 h0, l0, h1, l1;
                    split_bf16(v0, h0, l0);
                    split_bf16(v1, h1, l1);
                    if (which == 2) {
                        size_t o = ((size_t)(bb * H_ + hx) * D_ + d) * T_ + tt;
                        Vth[o] = h0; Vth[o + T_] = h1;
                        Vtl[o] = l0; Vtl[o + T_] = l1;
                    } else {
                        size_t o = ((size_t)(bb * H_ + hx) * T_ + tt) * D_ + d;
                        bf16* dh = (which == 0) ? Qh : Kh;
                        bf16* dl = (which == 0) ? Ql : Kl;
                        *(__nv_bfloat162*)&dh[o] = __nv_bfloat162(h0, h1);
                        *(__nv_bfloat162*)&dl[o] = __nv_bfloat162(l0, l1);
                    }
                } else if (EPI == EPI_BIAS_RESID) {
                    size_t o = (size_t)r * N + cc;
                    float2 bs = *(const float2*)&bias[cc];
                    float2 rs = *(const float2*)&resid[o];
                    *(float2*)&C[o] = make_float2(v0 + bs.x + rs.x, v1 + bs.y + rs.y);
                } else {
                    size_t o = (size_t)r * N + cc;
                    float2 bs = *(const float2*)&bias[cc];
                    float vv[2] = {v0 + bs.x, v1 + bs.y};
                    bf16 ph[2], pl[2];
                    #pragma unroll
                    for (int j = 0; j < 2; j++) {
                        float v = vv[j];
                        float u = 0.7978845608028654f * (v + 0.044715f * v * v * v);
                        v = 0.5f * v * (1.f + tanhf(u));
                        split_bf16(v, ph[j], pl[j]);
                    }
                    *(__nv_bfloat162*)&Chi[o] = __nv_bfloat162(ph[0], ph[1]);
                    *(__nv_bfloat162*)&Clo[o] = __nv_bfloat162(pl[0], pl[1]);
                }
            }
        }
    }
}

// ---------------- tensor-core flash attention ----------------
// 128q x 128kv tiles; 8 warps x 16 q-rows. Q/K bf16 hi/lo [BH,T,D]; Vt hi/lo [BH,D,T].
#define FROWK 144
#define FROWV 272
#define FQH   0
#define FQL   18432
#define FSTG0 36864
#define FSTGB 71680
// within stage: KH +0, KL +18432, VH +36864, VL +54272
#define FA2_SMEM (36864 + 2*FSTGB)   // 180224

__global__ void __launch_bounds__(256, 1)
flash_attn2(const bf16* __restrict__ Qh_g, const bf16* __restrict__ Ql_g,
            const bf16* __restrict__ Kh_g, const bf16* __restrict__ Kl_g,
            const bf16* __restrict__ Vth_g, const bf16* __restrict__ Vtl_g,
            bf16* __restrict__ ctxh, bf16* __restrict__ ctxl)
{
    extern __shared__ char sm[];
    const uint32_t sb = smem_u32(sm);
    const int tid = threadIdx.x, wid = tid >> 5, lid = tid & 31;
    const int bh = blockIdx.y;
    const int mtile = (gridDim.x - 1) - blockIdx.x;   // heavy tiles first
    const int q0 = mtile * 128;

    const bf16* Qhb = Qh_g + (size_t)bh * T_ * D_;
    const bf16* Qlb = Ql_g + (size_t)bh * T_ * D_;
    const bf16* Khb = Kh_g + (size_t)bh * T_ * D_;
    const bf16* Klb = Kl_g + (size_t)bh * T_ * D_;
    const bf16* Vhb = Vth_g + (size_t)bh * D_ * T_;
    const bf16* Vlb = Vtl_g + (size_t)bh * D_ * T_;

    // load Q tile (hi/lo)
    {
        const int row = tid >> 1, half = tid & 1;
        const char* gh = (const char*)(Qhb + (size_t)(q0 + row) * D_ + half * 32);
        const char* gl = (const char*)(Qlb + (size_t)(q0 + row) * D_ + half * 32);
        uint32_t dh = sb + FQH + row * FROWK + half * 64;
        uint32_t dl = sb + FQL + row * FROWK + half * 64;
        #pragma unroll
        for (int i = 0; i < 4; i++) { cpasync16(dh + i * 16, gh + i * 16); cpasync16(dl + i * 16, gl + i * 16); }
    }

    auto issueKV = [&](int stage, int kvt) {
        const int kv0 = kvt * 128;
        const uint32_t s0 = sb + FSTG0 + (uint32_t)stage * FSTGB;
        {
            const int row = tid >> 1, half = tid & 1;
            const char* gh = (const char*)(Khb + (size_t)(kv0 + row) * D_ + half * 32);
            const char* gl = (const char*)(Klb + (size_t)(kv0 + row) * D_ + half * 32);
            uint32_t dh = s0 + row * FROWK + half * 64;
            uint32_t dl = s0 + 18432 + row * FROWK + half * 64;
            #pragma unroll
            for (int i = 0; i < 4; i++) { cpasync16(dh + i * 16, gh + i * 16); cpasync16(dl + i * 16, gl + i * 16); }
        }
        {
            const int row = tid >> 2, qt = tid & 3;
            const char* gh = (const char*)(Vhb + (size_t)row * T_ + kv0 + qt * 32);
            const char* gl = (const char*)(Vlb + (size_t)row * T_ + kv0 + qt * 32);
            uint32_t dh = s0 + 36864 + row * FROWV + qt * 64;
            uint32_t dl = s0 + 54272 + row * FROWV + qt * 64;
            #pragma unroll
            for (int i = 0; i < 4; i++) { cpasync16(dh + i * 16, gh + i * 16); cpasync16(dl + i * 16, gl + i * 16); }
        }
        asm volatile("cp.async.commit_group;");
    };

    issueKV(0, 0);

    const int am = lid >> 3;
    uint32_t qhf[4][4], qlf[4][4];
    float m_[2] = {-1e30f, -1e30f}, l_[2] = {0.f, 0.f};
    float oacc[8][4] = {};

    const int r0g = q0 + wid * 16 + (lid >> 2);
    const int c0l = (lid & 3) * 2;

    for (int kt = 0; kt <= mtile; kt++) {
        if (kt + 1 <= mtile) { issueKV((kt + 1) & 1, kt + 1); asm volatile("cp.async.wait_group 1;"); }
        else                 { asm volatile("cp.async.wait_group 0;"); }
        __syncthreads();

        if (kt == 0) {
            const uint32_t rowq = wid * 16 + (am & 1) * 8 + (lid & 7);
            #pragma unroll
            for (int ks = 0; ks < 4; ks++) {
                uint32_t off = rowq * FROWK + ks * 32 + (am >> 1) * 16;
                ldsm4(qhf[ks], sb + FQH + off);
                ldsm4(qlf[ks], sb + FQL + off);
            }
        }

        const uint32_t stg = sb + FSTG0 + (uint32_t)(kt & 1) * FSTGB;

        // S = Q K^T (hi/lo 3-term)
        float sacc[16][4] = {};
        #pragma unroll
        for (int ks = 0; ks < 4; ks++) {
            #pragma unroll
            for (int ntp = 0; ntp < 8; ntp++) {
                uint32_t kh4[4], kl4[4];
                uint32_t off = (uint32_t)(ntp * 16 + ((lid >> 4) * 8) + (lid & 7)) * FROWK
                             + ks * 32 + ((lid >> 3) & 1) * 16;
                ldsm4(kh4, stg + off);
                ldsm4(kl4, stg + 18432 + off);
                mma_bf16(sacc[2 * ntp],     qhf[ks], kh4[0], kh4[1]);
                mma_bf16(sacc[2 * ntp],     qhf[ks], kl4[0], kl4[1]);
                mma_bf16(sacc[2 * ntp],     qlf[ks], kh4[0], kh4[1]);
                mma_bf16(sacc[2 * ntp + 1], qhf[ks], kh4[2], kh4[3]);
                mma_bf16(sacc[2 * ntp + 1], qhf[ks], kl4[2], kl4[3]);
                mma_bf16(sacc[2 * ntp + 1], qlf[ks], kh4[2], kh4[3]);
            }
        }

        // online softmax (rows warp-private; reduce over quad lanes)
        const bool diag = (kt == mtile);
        float mx0 = -1e30f, mx1 = -1e30f;
        #pragma unroll
        for (int nt = 0; nt < 16; nt++) {
            #pragma unroll
            for (int j = 0; j < 2; j++) {
                float s = sacc[nt][j] * 0.125f;
                if (diag && (kt * 128 + nt * 8 + c0l + j) > r0g) s = -1e30f;
                sacc[nt][j] = s; mx0 = fmaxf(mx0, s);
            }
            #pragma unroll
            for (int j = 2; j < 4; j++) {
                float s = sacc[nt][j] * 0.125f;
                if (diag && (kt * 128 + nt * 8 + c0l + j - 2) > r0g + 8) s = -1e30f;
                sacc[nt][j] = s; mx1 = fmaxf(mx1, s);
            }
        }
        #pragma unroll
        for (int o = 1; o < 4; o <<= 1) {
            mx0 = fmaxf(mx0, __shfl_xor_sync(0xffffffffu, mx0, o));
            mx1 = fmaxf(mx1, __shfl_xor_sync(0xffffffffu, mx1, o));
        }
        float mn0 = fmaxf(m_[0], mx0), mn1 = fmaxf(m_[1], mx1);
        float cr0 = __expf(m_[0] - mn0), cr1 = __expf(m_[1] - mn1);
        float sum0 = 0.f, sum1 = 0.f;
        #pragma unroll
        for (int nt = 0; nt < 16; nt++) {
            float p0 = __expf(sacc[nt][0] - mn0), p1 = __expf(sacc[nt][1] - mn0);
            float p2 = __expf(sacc[nt][2] - mn1), p3 = __expf(sacc[nt][3] - mn1);
            sacc[nt][0] = p0; sacc[nt][1] = p1; sacc[nt][2] = p2; sacc[nt][3] = p3;
            sum0 += p0 + p1; sum1 += p2 + p3;
        }
        #pragma unroll
        for (int o = 1; o < 4; o <<= 1) {
            sum0 += __shfl_xor_sync(0xffffffffu, sum0, o);
            sum1 += __shfl_xor_sync(0xffffffffu, sum1, o);
        }
        l_[0] = l_[0] * cr0 + sum0; l_[1] = l_[1] * cr1 + sum1;
        m_[0] = mn0; m_[1] = mn1;
        #pragma unroll
        for (int d = 0; d < 8; d++) {
            oacc[d][0] *= cr0; oacc[d][1] *= cr0;
            oacc[d][2] *= cr1; oacc[d][3] *= cr1;
        }

        // ctx += P V  (P hi/lo from registers; Vt B-frags)
        #pragma unroll
        for (int kvt = 0; kvt < 8; kvt++) {
            float p00 = sacc[2 * kvt][0],     p01 = sacc[2 * kvt][1];
            float p02 = sacc[2 * kvt][2],     p03 = sacc[2 * kvt][3];
            float p10 = sacc[2 * kvt + 1][0], p11 = sacc[2 * kvt + 1][1];
            float p12 = sacc[2 * kvt + 1][2], p13 = sacc[2 * kvt + 1][3];
            uint32_t pa_h[4], pa_l[4];
            pa_h[0] = packbf(p00, p01); pa_h[1] = packbf(p02, p03);
            pa_h[2] = packbf(p10, p11); pa_h[3] = packbf(p12, p13);
            bf16 b;
            b = __float2bfloat16(p00); float r00 = p00 - __bfloat162float(b);
            b = __float2bfloat16(p01); float r01 = p01 - __bfloat162float(b);
            b = __float2bfloat16(p02); float r02 = p02 - __bfloat162float(b);
            b = __float2bfloat16(p03); float r03 = p03 - __bfloat162float(b);
            b = __float2bfloat16(p10); float r10 = p10 - __bfloat162float(b);
            b = __float2bfloat16(p11); float r11 = p11 - __bfloat162float(b);
            b = __float2bfloat16(p12); float r12 = p12 - __bfloat162float(b);
            b = __float2bfloat16(p13); float r13 = p13 - __bfloat162float(b);
            pa_l[0] = packbf(r00, r01); pa_l[1] = packbf(r02, r03);
            pa_l[2] = packbf(r10, r11); pa_l[3] = packbf(r12, r13);

            #pragma unroll
            for (int ntp = 0; ntp < 4; ntp++) {
                uint32_t vh4[4], vl4[4];
                uint32_t off = (uint32_t)(ntp * 16 + ((lid >> 4) * 8) + (lid & 7)) * FROWV
                             + kvt * 32 + ((lid >> 3) & 1) * 16;
                ldsm4(vh4, stg + 36864 + off);
                ldsm4(vl4, stg + 54272 + off);
                mma_bf16(oacc[2 * ntp],     pa_h, vh4[0], vh4[1]);
                mma_bf16(oacc[2 * ntp],     pa_h, vl4[0], vl4[1]);
                mma_bf16(oacc[2 * ntp],     pa_l, vh4[0], vh4[1]);
                mma_bf16(oacc[2 * ntp + 1], pa_h, vh4[2], vh4[3]);
                mma_bf16(oacc[2 * ntp + 1], pa_h, vl4[2], vl4[3]);
                mma_bf16(oacc[2 * ntp + 1], pa_l, vh4[2], vh4[3]);
            }
        }
        __syncthreads();
    }

    // epilogue: normalize + split + store ctx [B,T,E]
    const int b = bh / H_, h = bh - b * H_;
    float inv0 = 1.f / l_[0], inv1 = 1.f / l_[1];
    #pragma unroll
    for (int nt = 0; nt < 8; nt++) {
        const int d = nt * 8 + c0l;
        {
            float v0 = oacc[nt][0] * inv0, v1 = oacc[nt][1] * inv0;
            bf16 h0, l0, h1, l1;
            split_bf16(v0, h0, l0); split_bf16(v1, h1, l1);
            size_t o = ((size_t)(b * T_ + r0g)) * E_ + h * D_ + d;
            *(__nv_bfloat162*)&ctxh[o] = __nv_bfloat162(h0, h1);
            *(__nv_bfloat162*)&ctxl[o] = __nv_bfloat162(l0, l1);
        }
        {
            float v0 = oacc[nt][2] * inv1, v1 = oacc[nt][3] * inv1;
            bf16 h0, l0, h1, l1;
            split_bf16(v0, h0, l0); split_bf16(v1, h1, l1);
            size_t o = ((size_t)(b * T_ + r0g + 8)) * E_ + h * D_ + d;
            *(__nv_bfloat162*)&ctxh[o] = __nv_bfloat162(h0, h1);
            *(__nv_bfloat162*)&ctxl[o] = __nv_bfloat162(l0, l1);
        }
    }
}

// ---------------- launch ----------------
extern "C" void kernel_launch(void* const* d_in, const int* in_sizes, int n_in,
                              void* d_out, int out_size)
{
    const float* x    = (const float*)d_in[0];
    const float* wq   = (const float*)d_in[1];
    const float* wk   = (const float*)d_in[2];
    const float* wv   = (const float*)d_in[3];
    const float* wo   = (const float*)d_in[4];
    const float* bo   = (const float*)d_in[5];
    const float* ln1s = (const float*)d_in[6];
    const float* ln1b = (const float*)d_in[7];
    const float* ln2s = (const float*)d_in[8];
    const float* ln2b = (const float*)d_in[9];
    const float* w1   = (const float*)d_in[10];
    const float* b1   = (const float*)d_in[11];
    const float* w2   = (const float*)d_in[12];
    const float* b2   = (const float*)d_in[13];
    float* out = (float*)d_out;

    float *x2;
    bf16 *h1h, *h1l, *qh, *ql, *kh, *kl, *vth, *vtl, *ctxh, *ctxl, *h2h, *h2l, *midh, *midl;
    bf16 *wqkvTh, *wqkvTl, *woTh, *woTl, *w1Th, *w1Tl, *w2Th, *w2Tl;
    cudaGetSymbolAddress((void**)&x2,  g_x2);
    cudaGetSymbolAddress((void**)&h1h, g_h1h);  cudaGetSymbolAddress((void**)&h1l, g_h1l);
    cudaGetSymbolAddress((void**)&qh,  g_qh);   cudaGetSymbolAddress((void**)&ql,  g_ql);
    cudaGetSymbolAddress((void**)&kh,  g_kh);   cudaGetSymbolAddress((void**)&kl,  g_kl);
    cudaGetSymbolAddress((void**)&vth, g_vth);  cudaGetSymbolAddress((void**)&vtl, g_vtl);
    cudaGetSymbolAddress((void**)&ctxh,g_ctxh); cudaGetSymbolAddress((void**)&ctxl,g_ctxl);
    cudaGetSymbolAddress((void**)&h2h, g_h2h);  cudaGetSymbolAddress((void**)&h2l, g_h2l);
    cudaGetSymbolAddress((void**)&midh,g_midh); cudaGetSymbolAddress((void**)&midl,g_midl);
    cudaGetSymbolAddress((void**)&wqkvTh,g_wqkvTh); cudaGetSymbolAddress((void**)&wqkvTl,g_wqkvTl);
    cudaGetSymbolAddress((void**)&woTh,g_woTh); cudaGetSymbolAddress((void**)&woTl,g_woTl);
    cudaGetSymbolAddress((void**)&w1Th,g_w1Th); cudaGetSymbolAddress((void**)&w1Tl,g_w1Tl);
    cudaGetSymbolAddress((void**)&w2Th,g_w2Th); cudaGetSymbolAddress((void**)&w2Tl,g_w2Tl);

    cudaFuncSetAttribute(flash_attn2, cudaFuncAttributeMaxDynamicSharedMemorySize, FA2_SMEM);
    cudaFuncSetAttribute(mma_gemm<EPI_QKV>,             cudaFuncAttributeMaxDynamicSharedMemorySize, GEMM_SMEM);
    cudaFuncSetAttribute(mma_gemm<EPI_BIAS_RESID>,      cudaFuncAttributeMaxDynamicSharedMemorySize, GEMM_SMEM);
    cudaFuncSetAttribute(mma_gemm<EPI_BIAS_GELU_SPLIT>, cudaFuncAttributeMaxDynamicSharedMemorySize, GEMM_SMEM);

    // weight transpose+split; wq/wk/wv stacked into [2304,768]
    wsplitT<<<dim3(E_/32,  E_/32), 256>>>(wq, wqkvTh,            wqkvTl,            E_, E_);
    wsplitT<<<dim3(E_/32,  E_/32), 256>>>(wk, wqkvTh + E_*E_,    wqkvTl + E_*E_,    E_, E_);
    wsplitT<<<dim3(E_/32,  E_/32), 256>>>(wv, wqkvTh + 2*E_*E_,  wqkvTl + 2*E_*E_,  E_, E_);
    wsplitT<<<dim3(E_/32,  E_/32), 256>>>(wo, woTh, woTl, E_, E_);
    wsplitT<<<dim3(FF_/32, E_/32), 256>>>(w1, w1Th, w1Tl, E_, FF_);
    wsplitT<<<dim3(E_/32, FF_/32), 256>>>(w2, w2Th, w2Tl, FF_, E_);

    // LN1 -> h1 hi/lo
    ln_kernel<<<M_, 256>>>(x, ln1s, ln1b, h1h, h1l);

    // fused QKV -> Q/K hi/lo [BH,T,D], Vt hi/lo [BH,D,T]
    mma_gemm<EPI_QKV><<<dim3(QKVN/128, M_/128), 256, GEMM_SMEM>>>(
        h1h, h1l, wqkvTh, wqkvTl, nullptr, nullptr, nullptr,
        qh, ql, kh, kl, vth, vtl, nullptr, nullptr, QKVN, E_);

    // tensor-core flash attention -> ctx hi/lo
    flash_attn2<<<dim3(T_/128, BH_), 256, FA2_SMEM>>>(qh, ql, kh, kl, vth, vtl, ctxh, ctxl);

    // proj + bias + resid -> x2
    mma_gemm<EPI_BIAS_RESID><<<dim3(E_/128, M_/128), 256, GEMM_SMEM>>>(
        ctxh, ctxl, woTh, woTl, bo, x, x2,
        nullptr, nullptr, nullptr, nullptr, nullptr, nullptr, nullptr, nullptr, E_, E_);

    // LN2 -> h2 hi/lo
    ln_kernel<<<M_, 256>>>(x2, ln2s, ln2b, h2h, h2l);

    // MLP1 (gelu) -> mid hi/lo
    mma_gemm<EPI_BIAS_GELU_SPLIT><<<dim3(FF_/128, M_/128), 256, GEMM_SMEM>>>(
        h2h, h2l, w1Th, w1Tl, b1, nullptr, nullptr,
        nullptr, nullptr, nullptr, nullptr, nullptr, nullptr, midh, midl, FF_, E_);

    // MLP2 + bias + resid -> out
    mma_gemm<EPI_BIAS_RESID><<<dim3(E_/128, M_/128), 256, GEMM_SMEM>>>(
        midh, midl, w2Th, w2Tl, b2, x2, out,
        nullptr, nullptr, nullptr, nullptr, nullptr, nullptr, nullptr, nullptr, E_, FF_);
}